// round 15
// baseline (speedup 1.0000x reference)
#include <cuda_runtime.h>
#include <cstdint>

#define NSEQ 128
#define TB   4096
#define FIN  208
#define HGRU 131
#define HP   132      // activation / h pitch: 33 quads
#define HPW  136      // W_hh row pitch
#define G3   393      // 3*H
#define G3P  416
#define DMLP 255
#define DOUT 17

#define GBLK 448      // GRU: 14 warps x 10 units x 3 gates (lanes 30,31 idle)
#define NREGP 50      // weight pairs in regs (quads 0..24)
#define NTAILQ 8      // weight quads in smem (quads 25..32)

typedef unsigned long long ull;

// ---- scratch (__device__ globals; zero-initialized; pads never written) ----
__device__ float g_wpad[G3 * HPW];
__device__ float g_gi[NSEQ * G3];
__device__ float g_x[NSEQ * HP];
__device__ float g_wiht[FIN * G3P];
__device__ float g_bihp[G3P];
__device__ float g_wmt[5][256 * 256];
__device__ float g_bmp[5][256];
__device__ float g_w6t[256 * 32];
__device__ float g_b6p[32];

// ---- prep1: only what gi_kernel needs (plus W_hh for gru) ----
__global__ void prep1_kernel(const float* __restrict__ Whh,
                             const float* __restrict__ Wih,
                             const float* __restrict__ bih)
{
    int idx = blockIdx.x * blockDim.x + threadIdx.x;

    if (idx < G3 * HGRU) {
        int j = idx / HGRU, k = idx - j * HGRU;
        g_wpad[j * HPW + k] = Whh[idx];
        return;
    }
    idx -= G3 * HGRU;
    if (idx < G3 * FIN) {
        int j = idx / FIN, k = idx - j * FIN;
        g_wiht[k * G3P + j] = Wih[idx];
        return;
    }
    idx -= G3 * FIN;
    if (idx < G3) g_bihp[idx] = bih[idx];
}

// ---- gi projection ----
__global__ __launch_bounds__(G3P) void gi_kernel(const float* __restrict__ hist)
{
    __shared__ float2 xs[FIN];
    const int j = threadIdx.x;
    const int r0 = blockIdx.x * 2;

    const float* h0 = hist + ((size_t)r0 * TB + (TB - 1)) * FIN;
    const float* h1 = hist + ((size_t)(r0 + 1) * TB + (TB - 1)) * FIN;
    for (int k = j; k < FIN; k += G3P) xs[k] = make_float2(h0[k], h1[k]);
    __syncthreads();

    float bv = g_bihp[j];
    float a0 = bv, a1 = bv;
#pragma unroll 16
    for (int k = 0; k < FIN; k++) {
        float w = g_wiht[k * G3P + j];
        float2 x = xs[k];
        a0 = fmaf(x.x, w, a0);
        a1 = fmaf(x.y, w, a1);
    }
    if (j < G3) {
        g_gi[r0 * G3 + j]       = a0;
        g_gi[(r0 + 1) * G3 + j] = a1;
    }
}

// ---- fused 6-layer MLP: 2 rows/CTA, staged 8-load batches (R14 proven) ----
__global__ __launch_bounds__(512) void mlp_kernel(float* __restrict__ out)
{
    __shared__ float2 xbuf[256];
    __shared__ float4 red[8][64][2];
    const int tid = threadIdx.x;
    const int cg = tid & 63;
    const int ks = tid >> 6;
    const int r0 = blockIdx.x * 2;
    const int kbase = ks * 32;

    if (tid < 256) {
        float2 v = make_float2(0.f, 0.f);
        if (tid < HGRU)
            v = make_float2(g_x[r0 * HP + tid], g_x[(r0 + 1) * HP + tid]);
        xbuf[tid] = v;
    }
    __syncthreads();

#pragma unroll
    for (int l = 0; l < 5; l++) {
        const float4* wt4 = reinterpret_cast<const float4*>(g_wmt[l]);
        float4 a0 = make_float4(0.f, 0.f, 0.f, 0.f);
        float4 a1 = a0;
#pragma unroll
        for (int g = 0; g < 4; g++) {
            float4 wb[8];
            float2 xb[8];
#pragma unroll
            for (int u = 0; u < 8; u++) {
                int k = kbase + g * 8 + u;
                wb[u] = wt4[k * 64 + cg];
                xb[u] = xbuf[k];
            }
#pragma unroll
            for (int u = 0; u < 8; u++) {
                a0.x = fmaf(xb[u].x, wb[u].x, a0.x);
                a0.y = fmaf(xb[u].x, wb[u].y, a0.y);
                a0.z = fmaf(xb[u].x, wb[u].z, a0.z);
                a0.w = fmaf(xb[u].x, wb[u].w, a0.w);
                a1.x = fmaf(xb[u].y, wb[u].x, a1.x);
                a1.y = fmaf(xb[u].y, wb[u].y, a1.y);
                a1.z = fmaf(xb[u].y, wb[u].z, a1.z);
                a1.w = fmaf(xb[u].y, wb[u].w, a1.w);
            }
        }
        red[ks][cg][0] = a0;
        red[ks][cg][1] = a1;
        __syncthreads();
        if (ks == 0) {
            float4 s0 = red[0][cg][0], s1 = red[0][cg][1];
#pragma unroll
            for (int q = 1; q < 8; q++) {
                float4 t0 = red[q][cg][0], t1 = red[q][cg][1];
                s0.x += t0.x; s0.y += t0.y; s0.z += t0.z; s0.w += t0.w;
                s1.x += t1.x; s1.y += t1.y; s1.z += t1.z; s1.w += t1.w;
            }
            float4 b = reinterpret_cast<const float4*>(g_bmp[l])[cg];
            xbuf[4 * cg + 0] = make_float2(fmaxf(s0.x + b.x, 0.f), fmaxf(s1.x + b.x, 0.f));
            xbuf[4 * cg + 1] = make_float2(fmaxf(s0.y + b.y, 0.f), fmaxf(s1.y + b.y, 0.f));
            xbuf[4 * cg + 2] = make_float2(fmaxf(s0.z + b.z, 0.f), fmaxf(s1.z + b.z, 0.f));
            xbuf[4 * cg + 3] = make_float2(fmaxf(s0.w + b.w, 0.f), fmaxf(s1.w + b.w, 0.f));
        }
        __syncthreads();
    }

    {
        const float4* w6 = reinterpret_cast<const float4*>(g_w6t);
        float4 a0 = make_float4(0.f, 0.f, 0.f, 0.f);
        float4 a1 = a0;
        if (cg < 8) {
#pragma unroll
            for (int g = 0; g < 4; g++) {
                float4 wb[8];
                float2 xb[8];
#pragma unroll
                for (int u = 0; u < 8; u++) {
                    int k = kbase + g * 8 + u;
                    wb[u] = w6[k * 8 + cg];
                    xb[u] = xbuf[k];
                }
#pragma unroll
                for (int u = 0; u < 8; u++) {
                    a0.x = fmaf(xb[u].x, wb[u].x, a0.x);
                    a0.y = fmaf(xb[u].x, wb[u].y, a0.y);
                    a0.z = fmaf(xb[u].x, wb[u].z, a0.z);
                    a0.w = fmaf(xb[u].x, wb[u].w, a0.w);
                    a1.x = fmaf(xb[u].y, wb[u].x, a1.x);
                    a1.y = fmaf(xb[u].y, wb[u].y, a1.y);
                    a1.z = fmaf(xb[u].y, wb[u].z, a1.z);
                    a1.w = fmaf(xb[u].y, wb[u].w, a1.w);
                }
            }
        }
        red[ks][cg][0] = a0;
        red[ks][cg][1] = a1;
        __syncthreads();
        if (ks == 0 && cg < 5) {
            float4 s0 = red[0][cg][0], s1 = red[0][cg][1];
#pragma unroll
            for (int q = 1; q < 8; q++) {
                float4 t0 = red[q][cg][0], t1 = red[q][cg][1];
                s0.x += t0.x; s0.y += t0.y; s0.z += t0.z; s0.w += t0.w;
                s1.x += t1.x; s1.y += t1.y; s1.z += t1.z; s1.w += t1.w;
            }
            float4 b = reinterpret_cast<const float4*>(g_b6p)[cg];
            float o0[4] = {s0.x + b.x, s0.y + b.y, s0.z + b.z, s0.w + b.w};
            float o1[4] = {s1.x + b.x, s1.y + b.y, s1.z + b.z, s1.w + b.w};
#pragma unroll
            for (int i = 0; i < 4; i++) {
                int c = 4 * cg + i;
                if (c < DOUT) {
                    out[r0 * DOUT + c]       = o0[i];
                    out[(r0 + 1) * DOUT + c] = o1[i];
                }
            }
        }
    }
}

// ---- GRU (block 0) + hidden MLP-weight prep (blocks 1..32) ----
__device__ __forceinline__ float tanh_fast(float x) {
    float y;
    asm("tanh.approx.f32 %0, %1;" : "=f"(y) : "f"(x));
    return y;
}
__device__ __forceinline__ float sigmoid_fast(float x) {
    return fmaf(0.5f, tanh_fast(0.5f * x), 0.5f);
}
__device__ __forceinline__ void fma2(ull& acc, ull h, ull w) {
    asm("fma.rn.f32x2 %0, %1, %2, %0;" : "+l"(acc) : "l"(h), "l"(w));
}

#define LDSQ(t0, t1, addr, off)                                      \
    asm volatile("ld.shared.v2.u64 {%0, %1}, [%2];"                  \
                 : "=l"(t0), "=l"(t1) : "r"((addr) + (off)))

__global__ __launch_bounds__(GBLK, 1) void gru_kernel(
    const float* __restrict__ b_hh,
    const float* __restrict__ W1, const float* __restrict__ b1,
    const float* __restrict__ W2, const float* __restrict__ b2,
    const float* __restrict__ W3, const float* __restrict__ b3,
    const float* __restrict__ W4, const float* __restrict__ b4,
    const float* __restrict__ W5, const float* __restrict__ b5,
    const float* __restrict__ W6, const float* __restrict__ b6)
{
    // blocks 1..32: MLP weight prep, fully hidden under block 0's recurrence
    if (blockIdx.x != 0) {
        const int total = DMLP * HGRU + 4 * DMLP * DMLP + 5 * DMLP
                        + DOUT * DMLP + DOUT;
        for (int idx = (blockIdx.x - 1) * GBLK + threadIdx.x;
             idx < total; idx += 32 * GBLK) {
            int t = idx;
            if (t < DMLP * HGRU) {
                int c = t / HGRU, k = t - c * HGRU;
                g_wmt[0][k * 256 + c] = W1[t];
                continue;
            }
            t -= DMLP * HGRU;
            if (t < 4 * DMLP * DMLP) {
                int l = t / (DMLP * DMLP);
                int r = t - l * (DMLP * DMLP);
                int c = r / DMLP, k = r - c * DMLP;
                const float* W = (l == 0) ? W2 : (l == 1) ? W3
                               : (l == 2) ? W4 : W5;
                g_wmt[l + 1][k * 256 + c] = W[r];
                continue;
            }
            t -= 4 * DMLP * DMLP;
            if (t < 5 * DMLP) {
                int l = t / DMLP, c = t - l * DMLP;
                const float* B = (l == 0) ? b1 : (l == 1) ? b2
                               : (l == 2) ? b3 : (l == 3) ? b4 : b5;
                g_bmp[l][c] = B[c];
                continue;
            }
            t -= 5 * DMLP;
            if (t < DOUT * DMLP) {
                int c = t / DMLP, k = t - c * DMLP;
                g_w6t[k * 32 + c] = W6[t];
                continue;
            }
            t -= DOUT * DMLP;
            g_b6p[t] = b6[t];
        }
        return;
    }

    __shared__ __align__(16) float hbuf[2][HP];      // ping-pong h (33 quads)
    __shared__ ulonglong2 tailq[NTAILQ][GBLK];       // weight quads 25..32

    const int tid  = threadIdx.x;
    const int lane = tid & 31;
    const int g    = lane % 3;                       // gate (r/z/n), lane<30
    const int u    = (tid >> 5) * 10 + lane / 3;     // unit
    const bool valid = (lane < 30) && (u < HGRU);
    const int row = valid ? (g * HGRU + u) : 0;
    const bool lead = valid && (g == 0);             // gate-math lane

    // weights for row: quads 0..24 in regs (50 pairs), 25..32 in smem
    ull w2[NREGP];
    float bj;
    {
        const ull* wr = reinterpret_cast<const ull*>(g_wpad + row * HPW);
#pragma unroll
        for (int i = 0; i < NREGP; i++) w2[i] = wr[i];
        const ulonglong2* wq = reinterpret_cast<const ulonglong2*>(wr);
#pragma unroll
        for (int t = 0; t < NTAILQ; t++) tailq[t][tid] = wq[25 + t];
        bj = b_hh[row];
    }
    if (tid < HP) { hbuf[0][tid] = 0.f; hbuf[1][tid] = 0.f; }

    uint32_t h_addr0;
    asm("{ .reg .u64 t; cvta.to.shared.u64 t, %1; cvt.u32.u64 %0, t; }"
        : "=r"(h_addr0) : "l"(&hbuf[0][0]));

    // gi prefetch: lead lanes hold all 3 gate inputs for their unit
    float gi0 = 0.f, gi1 = 0.f, gi2 = 0.f;
    if (lead) {
        gi0 = __ldg(g_gi + u);
        gi1 = __ldg(g_gi + u + HGRU);
        gi2 = __ldg(g_gi + u + 2 * HGRU);
    }
    float h_reg = 0.f;                               // h_prev (lead lanes)
    __syncthreads();

    for (int n = 0; n < NSEQ; n++) {
        float c0 = gi0, c1 = gi1, c2 = gi2;
        if (lead && n + 1 < NSEQ) {
            const float* gn = g_gi + (n + 1) * G3 + u;
            gi0 = __ldg(gn);
            gi1 = __ldg(gn + HGRU);
            gi2 = __ldg(gn + 2 * HGRU);
        }

        const int p = n & 1;
        const uint32_t ha = h_addr0 + p * (HP * 4);

        ull acc0, acc1 = 0ULL;
        asm("mov.b64 %0, {%1, %2};" : "=l"(acc0) : "f"(bj), "f"(0.f));

        // quads 0..23: 6 volatile-staged groups of 4
#pragma unroll
        for (int gg = 0; gg < 6; gg++) {
            ull t0, t1, t2, t3, t4, t5, t6, t7;
            LDSQ(t0, t1, ha, (4 * gg + 0) * 16);
            LDSQ(t2, t3, ha, (4 * gg + 1) * 16);
            LDSQ(t4, t5, ha, (4 * gg + 2) * 16);
            LDSQ(t6, t7, ha, (4 * gg + 3) * 16);
            fma2(acc0, t0, w2[8 * gg + 0]); fma2(acc1, t1, w2[8 * gg + 1]);
            fma2(acc0, t2, w2[8 * gg + 2]); fma2(acc1, t3, w2[8 * gg + 3]);
            fma2(acc0, t4, w2[8 * gg + 4]); fma2(acc1, t5, w2[8 * gg + 5]);
            fma2(acc0, t6, w2[8 * gg + 6]); fma2(acc1, t7, w2[8 * gg + 7]);
        }
        // quad 24 (pairs 48,49)
        {
            ull t0, t1;
            LDSQ(t0, t1, ha, 24 * 16);
            fma2(acc0, t0, w2[48]); fma2(acc1, t1, w2[49]);
        }
        // smem tail: quads 25..32 (plain loads)
        {
            const ulonglong2* hv2 =
                reinterpret_cast<const ulonglong2*>(hbuf[p]);
#pragma unroll
            for (int t = 0; t < NTAILQ; t += 4) {
                ulonglong2 h0 = hv2[25 + t];
                ulonglong2 h1 = hv2[26 + t];
                ulonglong2 h2 = hv2[27 + t];
                ulonglong2 h3 = hv2[28 + t];
                ulonglong2 wa = tailq[t][tid];
                ulonglong2 wb = tailq[t + 1][tid];
                ulonglong2 wc = tailq[t + 2][tid];
                ulonglong2 wd = tailq[t + 3][tid];
                fma2(acc0, h0.x, wa.x); fma2(acc1, h0.y, wa.y);
                fma2(acc0, h1.x, wb.x); fma2(acc1, h1.y, wb.y);
                fma2(acc0, h2.x, wc.x); fma2(acc1, h2.y, wc.y);
                fma2(acc0, h3.x, wd.x); fma2(acc1, h3.y, wd.y);
            }
        }

        float a0, a1, a2, a3;
        asm("mov.b64 {%0, %1}, %2;" : "=f"(a0), "=f"(a1) : "l"(acc0));
        asm("mov.b64 {%0, %1}, %2;" : "=f"(a2), "=f"(a3) : "l"(acc1));
        float d = (a0 + a2) + (a1 + a3);             // dot + b_hh[row]

        // in-warp gate combine: z/n rows are lanes +1/+2
        const unsigned m = 0xffffffffu;
        float s1 = __shfl_down_sync(m, d, 1);        // dot_z + bh_z
        float s2 = __shfl_down_sync(m, d, 2);        // dot_n + bh_n

        if (lead) {
            float r  = sigmoid_fast(c0 + d);
            float z  = sigmoid_fast(c1 + s1);
            float nn = tanh_fast(c2 + r * s2);
            float hnew = nn + z * (h_reg - nn);
            h_reg = hnew;
            hbuf[p ^ 1][u] = hnew;
            g_x[n * HP + u] = hnew;
        }
        __syncthreads();
    }
}

extern "C" void kernel_launch(void* const* d_in, const int* in_sizes, int n_in,
                              void* d_out, int out_size)
{
    const float* history = (const float*)d_in[0];
    const float* W_ih = (const float*)d_in[1];
    const float* W_hh = (const float*)d_in[2];
    const float* b_ih = (const float*)d_in[3];
    const float* b_hh = (const float*)d_in[4];
    const float* W1 = (const float*)d_in[5];  const float* b1 = (const float*)d_in[6];
    const float* W2 = (const float*)d_in[7];  const float* b2 = (const float*)d_in[8];
    const float* W3 = (const float*)d_in[9];  const float* b3 = (const float*)d_in[10];
    const float* W4 = (const float*)d_in[11]; const float* b4 = (const float*)d_in[12];
    const float* W5 = (const float*)d_in[13]; const float* b5 = (const float*)d_in[14];
    const float* W6 = (const float*)d_in[15]; const float* b6 = (const float*)d_in[16];
    float* out = (float*)d_out;

    const int prep1_total = G3 * HGRU + G3 * FIN + G3;

    prep1_kernel<<<(prep1_total + 511) / 512, 512>>>(W_hh, W_ih, b_ih); // 1
    gi_kernel<<<NSEQ / 2, G3P>>>(history);                              // 2
    gru_kernel<<<33, GBLK>>>(b_hh, W1, b1, W2, b2, W3, b3,              // 3
                             W4, b4, W5, b5, W6, b6);
    mlp_kernel<<<NSEQ / 2, 512>>>(out);                                 // 4 (profiled)
}

// round 16
// speedup vs baseline: 1.0524x; 1.0524x over previous
#include <cuda_runtime.h>
#include <cstdint>

#define NSEQ 128
#define TB   4096
#define FIN  208
#define HGRU 131
#define HP   132      // activation / h pitch: 33 quads
#define HPW  136      // W_hh row pitch
#define G3   393      // 3*H
#define G3P  416
#define DMLP 255
#define DOUT 17

#define GBLK 448      // GRU: 14 warps x 10 units x 3 gates (lanes 30,31 idle)
#define NREGP 50      // weight pairs in regs (quads 0..24)
#define NTAILQ 8      // weight quads in smem (quads 25..32)

typedef unsigned long long ull;

// ---- scratch (__device__ globals; zero-initialized; pads never written) ----
__device__ float g_wpad[G3 * HPW];
__device__ float g_gi[NSEQ * G3];
__device__ float g_x[NSEQ * HP];
__device__ float g_wiht[FIN * G3P];
__device__ float g_bihp[G3P];
__device__ float g_wmt[5][256 * 256];
__device__ float g_bmp[5][256];
__device__ float g_w6t[256 * 32];
__device__ float g_b6p[32];

// ---- prep: full weight prep (R14 version) ----
__global__ void prep_kernel(const float* __restrict__ Whh,
                            const float* __restrict__ Wih,
                            const float* __restrict__ bih,
                            const float* __restrict__ W1, const float* __restrict__ b1,
                            const float* __restrict__ W2, const float* __restrict__ b2,
                            const float* __restrict__ W3, const float* __restrict__ b3,
                            const float* __restrict__ W4, const float* __restrict__ b4,
                            const float* __restrict__ W5, const float* __restrict__ b5,
                            const float* __restrict__ W6, const float* __restrict__ b6)
{
    int idx = blockIdx.x * blockDim.x + threadIdx.x;

    if (idx < G3 * HGRU) {
        int j = idx / HGRU, k = idx - j * HGRU;
        g_wpad[j * HPW + k] = Whh[idx];
        return;
    }
    idx -= G3 * HGRU;
    if (idx < G3 * FIN) {
        int j = idx / FIN, k = idx - j * FIN;
        g_wiht[k * G3P + j] = Wih[idx];
        return;
    }
    idx -= G3 * FIN;
    if (idx < G3) { g_bihp[idx] = bih[idx]; return; }
    idx -= G3;
    if (idx < DMLP * HGRU) {
        int c = idx / HGRU, k = idx - c * HGRU;
        g_wmt[0][k * 256 + c] = W1[idx];
        return;
    }
    idx -= DMLP * HGRU;
    if (idx < 4 * DMLP * DMLP) {
        int l = idx / (DMLP * DMLP);
        int r = idx - l * (DMLP * DMLP);
        int c = r / DMLP, k = r - c * DMLP;
        const float* W = (l == 0) ? W2 : (l == 1) ? W3 : (l == 2) ? W4 : W5;
        g_wmt[l + 1][k * 256 + c] = W[r];
        return;
    }
    idx -= 4 * DMLP * DMLP;
    if (idx < 5 * DMLP) {
        int l = idx / DMLP, c = idx - l * DMLP;
        const float* B = (l == 0) ? b1 : (l == 1) ? b2 : (l == 2) ? b3
                        : (l == 3) ? b4 : b5;
        g_bmp[l][c] = B[c];
        return;
    }
    idx -= 5 * DMLP;
    if (idx < DOUT * DMLP) {
        int c = idx / DMLP, k = idx - c * DMLP;
        g_w6t[k * 32 + c] = W6[idx];
        return;
    }
    idx -= DOUT * DMLP;
    if (idx < DOUT) g_b6p[idx] = b6[idx];
}

// ---- gi projection ----
__global__ __launch_bounds__(G3P) void gi_kernel(const float* __restrict__ hist)
{
    __shared__ float2 xs[FIN];
    const int j = threadIdx.x;
    const int r0 = blockIdx.x * 2;

    const float* h0 = hist + ((size_t)r0 * TB + (TB - 1)) * FIN;
    const float* h1 = hist + ((size_t)(r0 + 1) * TB + (TB - 1)) * FIN;
    for (int k = j; k < FIN; k += G3P) xs[k] = make_float2(h0[k], h1[k]);
    __syncthreads();

    float bv = g_bihp[j];
    float a0 = bv, a1 = bv;
#pragma unroll 16
    for (int k = 0; k < FIN; k++) {
        float w = g_wiht[k * G3P + j];
        float2 x = xs[k];
        a0 = fmaf(x.x, w, a0);
        a1 = fmaf(x.y, w, a1);
    }
    if (j < G3) {
        g_gi[r0 * G3 + j]       = a0;
        g_gi[(r0 + 1) * G3 + j] = a1;
    }
}

// ---- fused 6-layer MLP: 2 rows/CTA, f32x2 column-pair FMAs ----
__device__ __forceinline__ void fma2m(ull& acc, ull x, ull w) {
    asm("fma.rn.f32x2 %0, %1, %2, %0;" : "+l"(acc) : "l"(x), "l"(w));
}
__device__ __forceinline__ ull dup_f32(float v) {
    ull d;
    asm("mov.b64 %0, {%1, %1};" : "=l"(d) : "f"(v));
    return d;
}
__device__ __forceinline__ float2 unpk(ull a) {
    float lo, hi;
    asm("mov.b64 {%0, %1}, %2;" : "=f"(lo), "=f"(hi) : "l"(a));
    return make_float2(lo, hi);
}

__global__ __launch_bounds__(512) void mlp_kernel(float* __restrict__ out)
{
    __shared__ ull xd0[256], xd1[256];     // activations duplicated (v,v)
    __shared__ float4 red[8][64][2];
    const int tid = threadIdx.x;
    const int cg = tid & 63;               // cols 4cg..4cg+3
    const int ks = tid >> 6;               // K-split 0..7
    const int r0 = blockIdx.x * 2;
    const int kbase = ks * 32;

    if (tid < 256) {
        float v0 = 0.f, v1 = 0.f;
        if (tid < HGRU) {
            v0 = g_x[r0 * HP + tid];
            v1 = g_x[(r0 + 1) * HP + tid];
        }
        xd0[tid] = dup_f32(v0);
        xd1[tid] = dup_f32(v1);
    }
    __syncthreads();

#pragma unroll
    for (int l = 0; l < 5; l++) {
        const ulonglong2* wtq = reinterpret_cast<const ulonglong2*>(g_wmt[l]);
        ull a00 = 0ULL, a01 = 0ULL, a10 = 0ULL, a11 = 0ULL;
#pragma unroll
        for (int g = 0; g < 4; g++) {
            ulonglong2 wb[8];
            ull x0b[8], x1b[8];
#pragma unroll
            for (int u = 0; u < 8; u++) {          // staged loads
                int k = kbase + g * 8 + u;
                wb[u] = wtq[k * 64 + cg];
                x0b[u] = xd0[k];
                x1b[u] = xd1[k];
            }
#pragma unroll
            for (int u = 0; u < 8; u++) {
                fma2m(a00, x0b[u], wb[u].x);       // row0, cols 4cg,4cg+1
                fma2m(a01, x0b[u], wb[u].y);       // row0, cols 4cg+2,+3
                fma2m(a10, x1b[u], wb[u].x);
                fma2m(a11, x1b[u], wb[u].y);
            }
        }
        {
            float2 p0 = unpk(a00), p1 = unpk(a01);
            float2 q0 = unpk(a10), q1 = unpk(a11);
            red[ks][cg][0] = make_float4(p0.x, p0.y, p1.x, p1.y);
            red[ks][cg][1] = make_float4(q0.x, q0.y, q1.x, q1.y);
        }
        __syncthreads();
        if (ks == 0) {
            float4 s0 = red[0][cg][0], s1 = red[0][cg][1];
#pragma unroll
            for (int q = 1; q < 8; q++) {
                float4 t0 = red[q][cg][0], t1 = red[q][cg][1];
                s0.x += t0.x; s0.y += t0.y; s0.z += t0.z; s0.w += t0.w;
                s1.x += t1.x; s1.y += t1.y; s1.z += t1.z; s1.w += t1.w;
            }
            float4 b = reinterpret_cast<const float4*>(g_bmp[l])[cg];
            xd0[4 * cg + 0] = dup_f32(fmaxf(s0.x + b.x, 0.f));
            xd0[4 * cg + 1] = dup_f32(fmaxf(s0.y + b.y, 0.f));
            xd0[4 * cg + 2] = dup_f32(fmaxf(s0.z + b.z, 0.f));
            xd0[4 * cg + 3] = dup_f32(fmaxf(s0.w + b.w, 0.f));
            xd1[4 * cg + 0] = dup_f32(fmaxf(s1.x + b.x, 0.f));
            xd1[4 * cg + 1] = dup_f32(fmaxf(s1.y + b.y, 0.f));
            xd1[4 * cg + 2] = dup_f32(fmaxf(s1.z + b.z, 0.f));
            xd1[4 * cg + 3] = dup_f32(fmaxf(s1.w + b.w, 0.f));
        }
        __syncthreads();
    }

    // layer 6: 17 outputs (weights padded to 32 cols; cg<8 active)
    {
        const ulonglong2* w6q = reinterpret_cast<const ulonglong2*>(g_w6t);
        ull a00 = 0ULL, a01 = 0ULL, a10 = 0ULL, a11 = 0ULL;
        if (cg < 8) {
#pragma unroll
            for (int g = 0; g < 4; g++) {
                ulonglong2 wb[8];
                ull x0b[8], x1b[8];
#pragma unroll
                for (int u = 0; u < 8; u++) {
                    int k = kbase + g * 8 + u;
                    wb[u] = w6q[k * 8 + cg];
                    x0b[u] = xd0[k];
                    x1b[u] = xd1[k];
                }
#pragma unroll
                for (int u = 0; u < 8; u++) {
                    fma2m(a00, x0b[u], wb[u].x);
                    fma2m(a01, x0b[u], wb[u].y);
                    fma2m(a10, x1b[u], wb[u].x);
                    fma2m(a11, x1b[u], wb[u].y);
                }
            }
        }
        {
            float2 p0 = unpk(a00), p1 = unpk(a01);
            float2 q0 = unpk(a10), q1 = unpk(a11);
            red[ks][cg][0] = make_float4(p0.x, p0.y, p1.x, p1.y);
            red[ks][cg][1] = make_float4(q0.x, q0.y, q1.x, q1.y);
        }
        __syncthreads();
        if (ks == 0 && cg < 5) {
            float4 s0 = red[0][cg][0], s1 = red[0][cg][1];
#pragma unroll
            for (int q = 1; q < 8; q++) {
                float4 t0 = red[q][cg][0], t1 = red[q][cg][1];
                s0.x += t0.x; s0.y += t0.y; s0.z += t0.z; s0.w += t0.w;
                s1.x += t1.x; s1.y += t1.y; s1.z += t1.z; s1.w += t1.w;
            }
            float4 b = reinterpret_cast<const float4*>(g_b6p)[cg];
            float o0[4] = {s0.x + b.x, s0.y + b.y, s0.z + b.z, s0.w + b.w};
            float o1[4] = {s1.x + b.x, s1.y + b.y, s1.z + b.z, s1.w + b.w};
#pragma unroll
            for (int i = 0; i < 4; i++) {
                int c = 4 * cg + i;
                if (c < DOUT) {
                    out[r0 * DOUT + c]       = o0[i];
                    out[(r0 + 1) * DOUT + c] = o1[i];
                }
            }
        }
    }
}

// ---- GRU: EXACT R14 (measured best: 113.4us cold / 148.2 total) ----
__device__ __forceinline__ float tanh_fast(float x) {
    float y;
    asm("tanh.approx.f32 %0, %1;" : "=f"(y) : "f"(x));
    return y;
}
__device__ __forceinline__ float sigmoid_fast(float x) {
    return fmaf(0.5f, tanh_fast(0.5f * x), 0.5f);
}
__device__ __forceinline__ void fma2(ull& acc, ull h, ull w) {
    asm("fma.rn.f32x2 %0, %1, %2, %0;" : "+l"(acc) : "l"(h), "l"(w));
}

#define LDSQ(t0, t1, addr, off)                                      \
    asm volatile("ld.shared.v2.u64 {%0, %1}, [%2];"                  \
                 : "=l"(t0), "=l"(t1) : "r"((addr) + (off)))

__global__ __launch_bounds__(GBLK, 1) void gru_kernel(const float* __restrict__ b_hh)
{
    __shared__ __align__(16) float hbuf[2][HP];      // ping-pong h (33 quads)
    __shared__ ulonglong2 tailq[NTAILQ][GBLK];       // weight quads 25..32

    const int tid  = threadIdx.x;
    const int lane = tid & 31;
    const int g    = lane % 3;                       // gate (r/z/n), lane<30
    const int u    = (tid >> 5) * 10 + lane / 3;     // unit
    const bool valid = (lane < 30) && (u < HGRU);
    const int row = valid ? (g * HGRU + u) : 0;

    // weights for row: quads 0..24 in regs (50 pairs), 25..32 in smem
    ull w2[NREGP];
    float bj;
    {
        const ull* wr = reinterpret_cast<const ull*>(g_wpad + row * HPW);
#pragma unroll
        for (int i = 0; i < NREGP; i++) w2[i] = wr[i];
        const ulonglong2* wq = reinterpret_cast<const ulonglong2*>(wr);
#pragma unroll
        for (int t = 0; t < NTAILQ; t++) tailq[t][tid] = wq[25 + t];
        bj = b_hh[row];
    }
    if (tid < HP) { hbuf[0][tid] = 0.f; hbuf[1][tid] = 0.f; }

    uint32_t h_addr0;
    asm("{ .reg .u64 t; cvta.to.shared.u64 t, %1; cvt.u32.u64 %0, t; }"
        : "=r"(h_addr0) : "l"(&hbuf[0][0]));

    float gi_v = __ldg(g_gi + row);                  // step-0 prefetch
    float h_reg = 0.f;                               // h_prev (g==0 threads)
    __syncthreads();

    for (int n = 0; n < NSEQ; n++) {
        float gi_cur = gi_v;
        if (n + 1 < NSEQ) gi_v = __ldg(g_gi + (n + 1) * G3 + row);

        const int p = n & 1;
        const uint32_t ha = h_addr0 + p * (HP * 4);

        ull acc0, acc1 = 0ULL;
        asm("mov.b64 %0, {%1, %2};" : "=l"(acc0) : "f"(bj), "f"(0.f));

        // quads 0..23: 6 volatile-staged groups of 4
#pragma unroll
        for (int gg = 0; gg < 6; gg++) {
            ull t0, t1, t2, t3, t4, t5, t6, t7;
            LDSQ(t0, t1, ha, (4 * gg + 0) * 16);
            LDSQ(t2, t3, ha, (4 * gg + 1) * 16);
            LDSQ(t4, t5, ha, (4 * gg + 2) * 16);
            LDSQ(t6, t7, ha, (4 * gg + 3) * 16);
            fma2(acc0, t0, w2[8 * gg + 0]); fma2(acc1, t1, w2[8 * gg + 1]);
            fma2(acc0, t2, w2[8 * gg + 2]); fma2(acc1, t3, w2[8 * gg + 3]);
            fma2(acc0, t4, w2[8 * gg + 4]); fma2(acc1, t5, w2[8 * gg + 5]);
            fma2(acc0, t6, w2[8 * gg + 6]); fma2(acc1, t7, w2[8 * gg + 7]);
        }
        // quad 24 (pairs 48,49)
        {
            ull t0, t1;
            LDSQ(t0, t1, ha, 24 * 16);
            fma2(acc0, t0, w2[48]); fma2(acc1, t1, w2[49]);
        }
        // smem tail: quads 25..32 (plain loads)
        {
            const ulonglong2* hv2 =
                reinterpret_cast<const ulonglong2*>(hbuf[p]);
#pragma unroll
            for (int t = 0; t < NTAILQ; t += 4) {
                ulonglong2 h0 = hv2[25 + t];
                ulonglong2 h1 = hv2[26 + t];
                ulonglong2 h2 = hv2[27 + t];
                ulonglong2 h3 = hv2[28 + t];
                ulonglong2 wa = tailq[t][tid];
                ulonglong2 wb = tailq[t + 1][tid];
                ulonglong2 wc = tailq[t + 2][tid];
                ulonglong2 wd = tailq[t + 3][tid];
                fma2(acc0, h0.x, wa.x); fma2(acc1, h0.y, wa.y);
                fma2(acc0, h1.x, wb.x); fma2(acc1, h1.y, wb.y);
                fma2(acc0, h2.x, wc.x); fma2(acc1, h2.y, wc.y);
                fma2(acc0, h3.x, wd.x); fma2(acc1, h3.y, wd.y);
            }
        }

        float a0, a1, a2, a3;
        asm("mov.b64 {%0, %1}, %2;" : "=f"(a0), "=f"(a1) : "l"(acc0));
        asm("mov.b64 {%0, %1}, %2;" : "=f"(a2), "=f"(a3) : "l"(acc1));
        float d = (a0 + a2) + (a1 + a3);             // dot + b_hh[row]

        // in-warp gate combine: z/n rows are lanes +1/+2
        const unsigned m = 0xffffffffu;
        float s1 = __shfl_down_sync(m, d, 1);        // dot_z + bh_z
        float s2 = __shfl_down_sync(m, d, 2);        // dot_n + bh_n
        float t1 = __shfl_down_sync(m, gi_cur, 1);   // i_z
        float t2 = __shfl_down_sync(m, gi_cur, 2);   // i_n

        if (valid && g == 0) {
            float r  = sigmoid_fast(gi_cur + d);
            float z  = sigmoid_fast(t1 + s1);
            float nn = tanh_fast(t2 + r * s2);
            float hnew = nn + z * (h_reg - nn);
            h_reg = hnew;
            hbuf[p ^ 1][u] = hnew;
            g_x[n * HP + u] = hnew;
        }
        __syncthreads();
    }
}

extern "C" void kernel_launch(void* const* d_in, const int* in_sizes, int n_in,
                              void* d_out, int out_size)
{
    const float* history = (const float*)d_in[0];
    const float* W_ih = (const float*)d_in[1];
    const float* W_hh = (const float*)d_in[2];
    const float* b_ih = (const float*)d_in[3];
    const float* b_hh = (const float*)d_in[4];
    const float* W1 = (const float*)d_in[5];  const float* b1 = (const float*)d_in[6];
    const float* W2 = (const float*)d_in[7];  const float* b2 = (const float*)d_in[8];
    const float* W3 = (const float*)d_in[9];  const float* b3 = (const float*)d_in[10];
    const float* W4 = (const float*)d_in[11]; const float* b4 = (const float*)d_in[12];
    const float* W5 = (const float*)d_in[13]; const float* b5 = (const float*)d_in[14];
    const float* W6 = (const float*)d_in[15]; const float* b6 = (const float*)d_in[16];
    float* out = (float*)d_out;

    const int prep_total = G3 * HGRU + G3 * FIN + G3 + DMLP * HGRU
                         + 4 * DMLP * DMLP + 5 * DMLP + DOUT * DMLP + DOUT;

    prep_kernel<<<(prep_total + 511) / 512, 512>>>(                 // launch 1
        W_hh, W_ih, b_ih, W1, b1, W2, b2, W3, b3, W4, b4, W5, b5, W6, b6);
    gi_kernel<<<NSEQ / 2, G3P>>>(history);                          // launch 2
    gru_kernel<<<1, GBLK>>>(b_hh);                                  // launch 3
    mlp_kernel<<<NSEQ / 2, 512>>>(out);                             // launch 4 (profiled)
}